// round 2
// baseline (speedup 1.0000x reference)
#include <cuda_runtime.h>

// Radon forward projection, sm_103a — round 2.
// Change vs R1: 384-thread blocks (2 angles concurrently) -> 36 warps/SM at
// occ 3, attacking the latency-bound profile (occ was 23%, issue 50.7%).

#define STRIDE 133               // row stride in floats (odd: conflict-free vertical rays)
#define PAD_ROWS 131             // original rows -1..129 (+1 shift)
#define SMEM_FLOATS (PAD_ROWS * STRIDE)
#define SMEM_BYTES (SMEM_FLOATS * 4)

#define N_IMGc 128
#define N_ANGc 285
#define N_DETc 183
#define GRID_X 55                // 55*8 = 440 blocks = 1 wave @ occ 3 on 148 SMs

__global__ __launch_bounds__(384, 3)
void radon_fp_kernel(const float* __restrict__ x, float* __restrict__ out)
{
    extern __shared__ float img[];
    const int tid = threadIdx.x;
    const int b = blockIdx.y;
    const int sub = tid / 192;       // which of the 2 concurrent angles
    const int det = tid % 192;

    // Zero padded image (border must stay 0)
    for (int i = tid; i < SMEM_FLOATS; i += 384) img[i] = 0.0f;
    __syncthreads();

    // Fill interior: original pixel (r,c) -> img[(r+1)*STRIDE + (c+1)]
    const float* gx = x + b * (N_IMGc * N_IMGc);
    for (int i = tid; i < N_IMGc * N_IMGc; i += 384) {
        int r = i >> 7, c = i & 127;
        img[(r + 1) * STRIDE + (c + 1)] = gx[i];
    }
    __syncthreads();

    const double RHOd = 28.284271247461902;   // 20*sqrt(2)
    const double DTd  = 2.0 * RHOd / 384.0;
    const double DXd  = 0.3125;               // 40/128
    const double PId  = 3.141592653589793;

    const double s  = -RHOd + (det + 0.5) * (2.0 * RHOd / 183.0);
    const double t0 = -RHOd + 0.5 * DTd;
    const float scale = (float)(DTd / 12.0);

    // Angle pairs p: angles {2p, 2p+1}; 285 angles -> p in [0, 142]
    for (int p = blockIdx.x; 2 * p < N_ANGc; p += GRID_X) {
        int a = 2 * p + sub;
        if (det < N_DETc && a < N_ANGc) {
            double ang = (a + 0.5) * (PId / (double)N_ANGc);
            double sn = sin(ang), cs = cos(ang);

            // i0 = ((-s*sn + t*cs) + 20)/DX - 0.5,  t = t0 + k*DT
            double d0 = DTd * cs / DXd;
            double d1 = DTd * sn / DXd;
            double c0 = ((-s * sn + t0 * cs) + 20.0) / DXd - 0.5;
            double c1 = (( s * cs + t0 * sn) + 20.0) / DXd - 0.5;

            // Valid (nonzero, memory-safe) index window [-0.999, 128.5]
            const double LO = -0.999, HI = 128.5;
            double klo = 0.0, khi = 383.0;

            if (d0 > 1e-9)       { klo = fmax(klo, (LO - c0) / d0); khi = fmin(khi, (HI - c0) / d0); }
            else if (d0 < -1e-9) { klo = fmax(klo, (HI - c0) / d0); khi = fmin(khi, (LO - c0) / d0); }
            else if (c0 < LO || c0 > HI) khi = -1.0;

            if (d1 > 1e-9)       { klo = fmax(klo, (LO - c1) / d1); khi = fmin(khi, (HI - c1) / d1); }
            else if (d1 < -1e-9) { klo = fmax(klo, (HI - c1) / d1); khi = fmin(khi, (LO - c1) / d1); }
            else if (c1 < LO || c1 > HI) khi = -1.0;

            klo = fmin(fmax(klo, 0.0), 500.0);
            khi = fmin(fmax(khi, -1.0), 383.0);
            int k0 = (int)ceil(klo);
            int k1 = (int)floor(khi);

            float c0f = (float)c0, d0f = (float)d0;
            float c1f = (float)c1, d1f = (float)d1;
            float acc = 0.0f;
            float kf = (float)k0;    // exact float counter, avoids per-iter I2F

            #pragma unroll 4
            for (int k = k0; k <= k1; ++k, kf += 1.0f) {
                float i0 = fmaf(kf, d0f, c0f);
                float i1 = fmaf(kf, d1f, c1f);
                float x0f = floorf(i0);
                float x1f = floorf(i1);
                int x0 = (int)x0f;
                int x1 = (int)x1f;
                float f0 = i0 - x0f;
                float f1 = i1 - x1f;
                const float* p4 = img + (x0 * STRIDE + x1 + (STRIDE + 1));
                float v00 = p4[0];
                float v01 = p4[1];
                float v10 = p4[STRIDE];
                float v11 = p4[STRIDE + 1];
                float top = fmaf(f1, v01 - v00, v00);
                float bot = fmaf(f1, v11 - v10, v10);
                acc += fmaf(f0, bot - top, top);
            }

            out[(b * N_ANGc + a) * N_DETc + det] = acc * scale;
        }
    }
}

extern "C" void kernel_launch(void* const* d_in, const int* in_sizes, int n_in,
                              void* d_out, int out_size)
{
    const float* x = (const float*)d_in[0];
    float* out = (float*)d_out;

    cudaFuncSetAttribute(radon_fp_kernel,
                         cudaFuncAttributeMaxDynamicSharedMemorySize, SMEM_BYTES);

    dim3 grid(GRID_X, 8);
    radon_fp_kernel<<<grid, 384, SMEM_BYTES>>>(x, out);
}

// round 3
// speedup vs baseline: 2.0842x; 2.0842x over previous
#include <cuda_runtime.h>

// Radon forward projection, sm_103a — round 3.
// Two batches packed per smem entry (float2) -> every LDS.64 / f32x2 op serves
// 2 samples. Magic-number rounding removes F2I from the address chain. All
// per-ray setup in fp32 (double sincospi once per angle via tid<8 + smem).

#define STRIDE_E 131
#define ROWS_E   131
#define SMEM_ELEMS (ROWS_E * STRIDE_E)        // 17161 entries (8 B each)
#define SMEM_BYTES (SMEM_ELEMS * 8 + 64)      // + trig table

#define N_ANG 285
#define N_DET 183
#define GRID_A 37                              // 37 * 4 batch-pairs = 148 blocks

typedef unsigned long long u64;

__device__ __forceinline__ u64 pk2(float x, float y) {
    u64 u; asm("mov.b64 %0, {%1, %2};" : "=l"(u) : "f"(x), "f"(y)); return u;
}
__device__ __forceinline__ void upk2(u64 u, float& x, float& y) {
    asm("mov.b64 {%0, %1}, %2;" : "=f"(x), "=f"(y) : "l"(u));
}
__device__ __forceinline__ u64 fma2_(u64 a, u64 b, u64 c) {
    u64 d; asm("fma.rn.f32x2 %0, %1, %2, %3;" : "=l"(d) : "l"(a), "l"(b), "l"(c)); return d;
}
__device__ __forceinline__ u64 add2_(u64 a, u64 b) {
    u64 d; asm("add.rn.f32x2 %0, %1, %2;" : "=l"(d) : "l"(a), "l"(b)); return d;
}

__global__ __launch_bounds__(384, 1)
void radon_fp_kernel(const float* __restrict__ x, float* __restrict__ out)
{
    extern __shared__ u64 imgs[];
    float2* trig = (float2*)(imgs + SMEM_ELEMS);

    const int tid = threadIdx.x;
    const int bp  = blockIdx.y;          // batch pair: batches 2bp, 2bp+1
    const int sub = tid / 192;           // which of 2 concurrent angles
    const int det = tid % 192;

    const float* gx0 = x + (2 * bp)     * 16384;
    const float* gx1 = x + (2 * bp + 1) * 16384;

    // Fill padded dual-batch image: entry (ar, ac) = pixel (ar-1, ac-1), border 0.
    for (int e = tid; e < SMEM_ELEMS; e += 384) {
        int ar = e / STRIDE_E;
        int ac = e - ar * STRIDE_E;
        int pr = ar - 1, pc = ac - 1;
        bool in = ((unsigned)pr < 128u) & ((unsigned)pc < 128u);
        int gi = pr * 128 + pc;
        float v0 = in ? gx0[gi] : 0.0f;
        float v1 = in ? gx1[gi] : 0.0f;
        imgs[e] = pk2(v0, v1);
    }
    // Double-precision trig once per angle (<=8 angles per block), rest fp32.
    if (tid < 8) {
        int jp = tid >> 1, sb = tid & 1;
        int p = blockIdx.x + jp * GRID_A;
        int a = 2 * p + sb;
        if (p < 143 && a < N_ANG) {
            double sd, cd;
            sincospi((a + 0.5) / 285.0, &sd, &cd);
            trig[tid] = make_float2((float)sd, (float)cd);
        }
    }
    __syncthreads();

    // Constants (double-derived)
    const float RHOf = 28.284271247461902f;
    const float DTf  = 0.14731391274719688f;        // 2*RHO/384
    const float KD   = 0.47140452079103173f;        // DT/DX, DX = 0.3125
    const float t0c  = -28.284271247461902f + 0.5f * 0.14731391274719688f;
    const float scale = 0.012276159395599740f;      // DT/12
    const float s = fmaf((float)det + 0.5f, 2.0f * RHOf / 183.0f, -RHOf);

    const u64 BIG2   = pk2( 8388608.f,  8388608.f);
    const u64 nBIG2  = pk2(-8388608.f, -8388608.f);
    const u64 half2c = pk2(0.5f, 0.5f);
    const u64 neg1   = pk2(-1.f, -1.f);
    const u64 one2   = pk2(1.f, 1.f);
    const u64* imgm = imgs - 132;    // folds (x0+1)*131 + (x1+1) = flp0*131+flp1-132

    int jp = 0;
    for (int p = blockIdx.x; p < 143; p += GRID_A, ++jp) {
        int a = 2 * p + sub;
        if (det < N_DET && a < N_ANG) {
            float2 sc = trig[jp * 2 + sub];
            float sn = sc.x, cs = sc.y;
            float d0 = KD * cs;
            float d1 = KD * sn;
            // i0 = (-s*sn + t*cs + 20)*3.2 - 0.5, t = t0c + k*DT
            float c0 = fmaf(-s, sn, fmaf(t0c, cs, 20.0f)) * 3.2f - 0.5f;
            float c1 = fmaf( s, cs, fmaf(t0c, sn, 20.0f)) * 3.2f - 0.5f;

            // Valid window (content zero outside i in (-1, 128); safe to 129.49)
            const float LO = -0.999f, HI = 128.01f;
            float ra = (LO - c0) / d0, rb = (HI - c0) / d0;
            float klo = fmaxf(0.0f,  fminf(ra, rb));
            float khi = fminf(383.0f, fmaxf(ra, rb));
            ra = (LO - c1) / d1; rb = (HI - c1) / d1;
            klo = fmaxf(klo, fminf(ra, rb));
            khi = fminf(khi, fmaxf(ra, rb));
            int k0 = (int)ceilf(klo);
            int k1 = (int)floorf(khi);

            u64 d01  = pk2(d0, d1);
            u64 c01m = pk2(c0 + 1.5f, c1 + 1.5f);   // t = i + 1.5
            u64 kf2  = pk2((float)k0, (float)k0);
            u64 acc2 = 0ull;

            #pragma unroll 4
            for (int k = k0; k <= k1; ++k) {
                u64 t01  = fma2_(kf2, d01, c01m);        // i+1.5, both axes
                u64 y01  = add2_(t01, BIG2);             // round-to-int in mantissa
                u64 fl01 = add2_(y01, nBIG2);            // round(t) = floor(i)+2
                u64 fr01 = add2_(fma2_(fl01, neg1, t01), half2c); // frac in [0,1]
                kf2 = add2_(kf2, one2);
                float yl, yh; upk2(y01, yl, yh);
                int n0 = __float_as_int(yl) & 255;       // floor(i0)+2 in [1,130]
                int n1 = __float_as_int(yh) & 255;
                int idx = n0 * STRIDE_E + n1;
                u64 p00 = imgm[idx];
                u64 p01 = imgm[idx + 1];
                u64 p10 = imgm[idx + STRIDE_E];
                u64 p11 = imgm[idx + STRIDE_E + 1];
                float f0, f1; upk2(fr01, f0, f1);
                u64 f0_2 = pk2(f0, f0);
                u64 f1_2 = pk2(f1, f1);
                u64 m0  = fma2_(f1_2, fma2_(p00, neg1, p01), p00);
                u64 m1  = fma2_(f1_2, fma2_(p10, neg1, p11), p10);
                u64 res = fma2_(f0_2, fma2_(m0, neg1, m1), m0);
                acc2 = add2_(acc2, res);
            }

            float o0, o1; upk2(acc2, o0, o1);
            int ob = ((2 * bp) * N_ANG + a) * N_DET + det;
            out[ob] = o0 * scale;
            out[ob + N_ANG * N_DET] = o1 * scale;
        }
    }
}

extern "C" void kernel_launch(void* const* d_in, const int* in_sizes, int n_in,
                              void* d_out, int out_size)
{
    const float* x = (const float*)d_in[0];
    float* out = (float*)d_out;

    cudaFuncSetAttribute(radon_fp_kernel,
                         cudaFuncAttributeMaxDynamicSharedMemorySize, SMEM_BYTES);

    dim3 grid(GRID_A, 4);
    radon_fp_kernel<<<grid, 384, SMEM_BYTES>>>(x, out);
}